// round 14
// baseline (speedup 1.0000x reference)
#include <cuda_runtime.h>
#include <cuda_bf16.h>
#include <cstdint>
#include <cstddef>

#define D_MODEL 1024
#define N_HEADS 16
#define DK      64
#define BATCH   4
#define SEQ     2048
#define MTOT    (BATCH * SEQ)     // 8192
#define BH      (BATCH * N_HEADS) // 64

// ---------------- device global scratch (no allocation APIs allowed) --------
__device__ __nv_bfloat16 g_A_hi[(size_t)MTOT * D_MODEL];         // GEMM A input (x, then attn)
__device__ __nv_bfloat16 g_A_lo[(size_t)MTOT * D_MODEL];
__device__ __nv_bfloat16 g_Wq_hi[(size_t)3 * D_MODEL * D_MODEL]; // [3072][1024] K-major
__device__ __nv_bfloat16 g_Wq_lo[(size_t)3 * D_MODEL * D_MODEL];
__device__ __nv_bfloat16 g_Wp_hi[(size_t)D_MODEL * D_MODEL];
__device__ __nv_bfloat16 g_Wp_lo[(size_t)D_MODEL * D_MODEL];
// flash operands, per (b,h) planar  (written directly by QKV GEMM epilogue)
__device__ __nv_bfloat16 g_Qh[(size_t)BH * SEQ * DK];            // [bh][t][64], pre-scaled
__device__ __nv_bfloat16 g_Ql[(size_t)BH * SEQ * DK];
__device__ __nv_bfloat16 g_Kh[(size_t)BH * SEQ * DK];
__device__ __nv_bfloat16 g_Kl[(size_t)BH * SEQ * DK];
__device__ __nv_bfloat16 g_Vh[(size_t)BH * SEQ * DK];            // [bh][t][64] (pre-transpose)
__device__ __nv_bfloat16 g_Vl[(size_t)BH * SEQ * DK];
__device__ __nv_bfloat16 g_Vth[(size_t)BH * DK * SEQ];           // [bh][d][t]  (V transposed)
__device__ __nv_bfloat16 g_Vtl[(size_t)BH * DK * SEQ];

// ---------------- arch-agnostic PTX helpers (sm_80+ only) ------------------
__device__ __forceinline__ uint32_t smem_to_u32(const void* p) {
    uint32_t a;
    asm("{ .reg .u64 t; cvta.to.shared.u64 t, %1; cvt.u32.u64 %0, t; }"
        : "=r"(a) : "l"(p));
    return a;
}
__device__ __forceinline__ void cp_async16(uint32_t dst, const void* src) {
    asm volatile("cp.async.cg.shared.global [%0], [%1], 16;\n" :: "r"(dst), "l"(src));
}
__device__ __forceinline__ void cp_commit() {
    asm volatile("cp.async.commit_group;\n" ::: "memory");
}
template <int N>
__device__ __forceinline__ void cp_wait() {
    asm volatile("cp.async.wait_group %0;\n" :: "n"(N) : "memory");
}
__device__ __forceinline__ void mma_bf16(float* d, const uint32_t* a, const uint32_t* b) {
    asm volatile(
        "mma.sync.aligned.m16n8k16.row.col.f32.bf16.bf16.f32 "
        "{%0,%1,%2,%3}, {%4,%5,%6,%7}, {%8,%9}, {%0,%1,%2,%3};\n"
        : "+f"(d[0]), "+f"(d[1]), "+f"(d[2]), "+f"(d[3])
        : "r"(a[0]), "r"(a[1]), "r"(a[2]), "r"(a[3]), "r"(b[0]), "r"(b[1]));
}
// ldmatrix x4: 4 fragment regs in one instruction (sm_75+)
__device__ __forceinline__ void ldsm_x4(uint32_t* r, uint32_t addr) {
    asm volatile("ldmatrix.sync.aligned.m8n8.x4.shared.b16 {%0,%1,%2,%3}, [%4];"
        : "=r"(r[0]), "=r"(r[1]), "=r"(r[2]), "=r"(r[3]) : "r"(addr));
}
// split two fp32 into packed bf16x2 hi and lo-residual
__device__ __forceinline__ void split2(float x, float y, uint32_t& hi, uint32_t& lo) {
    __nv_bfloat16 hx = __float2bfloat16(x), hy = __float2bfloat16(y);
    __nv_bfloat16 lx = __float2bfloat16(x - __bfloat162float(hx));
    __nv_bfloat16 ly = __float2bfloat16(y - __bfloat162float(hy));
    __nv_bfloat162 hp(hx, hy), lp(lx, ly);
    hi = *(uint32_t*)&hp; lo = *(uint32_t*)&lp;
}

// ---------------------------------------------------------------------------
// Prepass: split fp32 x into bf16 hi/lo (GEMM A input).
// ---------------------------------------------------------------------------
__global__ __launch_bounds__(256) void aprep_kernel(const float* __restrict__ xin)
{
    size_t i = ((size_t)blockIdx.x * 256 + threadIdx.x) * 4;
    float4 v = *(const float4*)(xin + i);
    uint32_t h0, l0, h1, l1;
    split2(v.x, v.y, h0, l0);
    split2(v.z, v.w, h1, l1);
    *(uint2*)(g_A_hi + i) = make_uint2(h0, h1);
    *(uint2*)(g_A_lo + i) = make_uint2(l0, l1);
}

// ---------------------------------------------------------------------------
// Prepass: transpose W [1024][N] -> [N][1024] and split hi/lo.
// ---------------------------------------------------------------------------
template <int WHICH>
__global__ __launch_bounds__(256) void wprep_kernel(const float* __restrict__ W, int N)
{
    __shared__ float t[32][33];
    const int n0 = blockIdx.x * 32, k0 = blockIdx.y * 32;
    const int tx = threadIdx.x, ty = threadIdx.y;
    #pragma unroll
    for (int i = 0; i < 4; i++)
        t[ty + 8 * i][tx] = W[(size_t)(k0 + ty + 8 * i) * N + n0 + tx];
    __syncthreads();
    __nv_bfloat16* hi = (WHICH == 0) ? g_Wq_hi : g_Wp_hi;
    __nv_bfloat16* lo = (WHICH == 0) ? g_Wq_lo : g_Wp_lo;
    #pragma unroll
    for (int i = 0; i < 4; i++) {
        int n = n0 + ty + 8 * i, k = k0 + tx;
        float v = t[tx][ty + 8 * i];
        __nv_bfloat16 h = __float2bfloat16(v);
        hi[(size_t)n * D_MODEL + k] = h;
        lo[(size_t)n * D_MODEL + k] = __float2bfloat16(v - __bfloat162float(h));
    }
}

// ---------------------------------------------------------------------------
// bf16x3 GEMM via mma.sync.m16n8k16 + ldmatrix.  (unchanged, passing)
// IS_QKV: fused epilogue writes planar bf16 hi/lo Q (x0.125) / K / V directly.
// ---------------------------------------------------------------------------
#define GPITCH 80
#define TSZ    10240
#define BUFSZ  40960

template <bool IS_QKV>
__global__ __launch_bounds__(256, 2) void mma_gemm(float* __restrict__ Cparam)
{
    extern __shared__ char smem[];
    const int N = IS_QKV ? 3 * D_MODEL : D_MODEL;
    const __nv_bfloat16* BhiG = IS_QKV ? g_Wq_hi : g_Wp_hi;
    const __nv_bfloat16* BloG = IS_QKV ? g_Wq_lo : g_Wp_lo;

    const int tid = threadIdx.x;
    const int wid = tid >> 5, lane = tid & 31;
    const int wm = wid & 3, wn = wid >> 2;
    const int g = lane >> 2, q = lane & 3;
    const int m0 = blockIdx.y * 128, n0 = blockIdx.x * 128;

    const char* srcs[4] = {
        (const char*)(g_A_hi + (size_t)m0 * D_MODEL),
        (const char*)(g_A_lo + (size_t)m0 * D_MODEL),
        (const char*)(BhiG + (size_t)n0 * D_MODEL),
        (const char*)(BloG + (size_t)n0 * D_MODEL) };

    const uint32_t sb = smem_to_u32(smem);

    const uint32_t aOff = (uint32_t)(wm * 32 + (lane & 15)) * GPITCH + (lane >> 4) * 16;
    const uint32_t bOff = 2 * TSZ +
        (uint32_t)(wn * 64 + ((lane >> 4) & 1) * 8 + (lane & 7)) * GPITCH +
        ((lane >> 3) & 1) * 16;

    float acc[2][8][4] = {};

    auto issue = [&](int c) {
        const uint32_t buf = sb + (c & 1) * BUFSZ;
        const size_t koff = (size_t)c * 64;
        #pragma unroll
        for (int i = 0; i < 8; i++) {
            int id = tid + i * 256;
            int t = id >> 9;
            int rem = id & 511;
            int row = rem >> 2, c16 = rem & 3;
            cp_async16(buf + t * TSZ + row * GPITCH + c16 * 16,
                       srcs[t] + (size_t)row * 2048 + koff + c16 * 16);
        }
        cp_commit();
    };

    issue(0);
    #pragma unroll 1
    for (int c = 0; c < 32; c++) {
        if (c + 1 < 32) { issue(c + 1); cp_wait<1>(); }
        else            { cp_wait<0>(); }
        __syncthreads();

        const uint32_t buf = sb + (c & 1) * BUFSZ;
        #pragma unroll
        for (int ks = 0; ks < 2; ks++) {
            const uint32_t ksb = ks * 32;
            uint32_t ah[2][4], al[2][4], bh[4][4], bl[4][4];
            #pragma unroll
            for (int am = 0; am < 2; am++) {
                const uint32_t a = buf + aOff + (uint32_t)am * 16 * GPITCH + ksb;
                ldsm_x4(ah[am], a);
                ldsm_x4(al[am], a + TSZ);
            }
            #pragma unroll
            for (int j = 0; j < 4; j++) {
                const uint32_t a = buf + bOff + (uint32_t)j * 16 * GPITCH + ksb;
                ldsm_x4(bh[j], a);
                ldsm_x4(bl[j], a + TSZ);
            }
            #pragma unroll
            for (int am = 0; am < 2; am++)
                #pragma unroll
                for (int j = 0; j < 4; j++) {
                    mma_bf16(acc[am][2 * j],     ah[am], &bh[j][0]);
                    mma_bf16(acc[am][2 * j],     ah[am], &bl[j][0]);
                    mma_bf16(acc[am][2 * j],     al[am], &bh[j][0]);
                    mma_bf16(acc[am][2 * j + 1], ah[am], &bh[j][2]);
                    mma_bf16(acc[am][2 * j + 1], ah[am], &bl[j][2]);
                    mma_bf16(acc[am][2 * j + 1], al[am], &bh[j][2]);
                }
        }
        __syncthreads();
    }

    if (IS_QKV) {
        // fused epilogue: split hi/lo, write planar [bh][t][64]
        const int region = n0 >> 10;                         // 0=Q, 1=K, 2=V
        __nv_bfloat16* dsthi = (region == 0) ? g_Qh : (region == 1) ? g_Kh : g_Vh;
        __nv_bfloat16* dstlo = (region == 0) ? g_Ql : (region == 1) ? g_Kl : g_Vl;
        const float scale = (region == 0) ? 0.125f : 1.0f;
        const int crbase = (n0 & 1023) + wn * 64;
        const int b = m0 >> 11;                              // batch (tiles don't span)
        #pragma unroll
        for (int am = 0; am < 2; am++) {
            const int t0 = (m0 & 2047) + wm * 32 + am * 16 + g;
            #pragma unroll
            for (int an = 0; an < 8; an++) {
                const int cr = crbase + an * 8 + q * 2;
                const int h = cr >> 6, d = cr & 63;
                const size_t base = (((size_t)(b * 16 + h)) * SEQ + t0) * DK + d;
                uint32_t hi, lo;
                split2(acc[am][an][0] * scale, acc[am][an][1] * scale, hi, lo);
                *(uint32_t*)(dsthi + base) = hi;
                *(uint32_t*)(dstlo + base) = lo;
                split2(acc[am][an][2] * scale, acc[am][an][3] * scale, hi, lo);
                *(uint32_t*)(dsthi + base + 8 * DK) = hi;
                *(uint32_t*)(dstlo + base + 8 * DK) = lo;
            }
        }
    } else {
        #pragma unroll
        for (int am = 0; am < 2; am++) {
            const int row = m0 + wm * 32 + am * 16 + g;
            #pragma unroll
            for (int an = 0; an < 8; an++) {
                const int col = n0 + wn * 64 + an * 8 + q * 2;
                *(float2*)(Cparam + (size_t)row * N + col) =
                    make_float2(acc[am][an][0], acc[am][an][1]);
                *(float2*)(Cparam + (size_t)(row + 8) * N + col) =
                    make_float2(acc[am][an][2], acc[am][an][3]);
            }
        }
    }
}

// ---------------------------------------------------------------------------
// vtrans: bf16 V [bh][t][64] -> V^T [bh][d][2048] (hi and lo).
// ---------------------------------------------------------------------------
__global__ __launch_bounds__(256) void vtrans_kernel()
{
    __shared__ __nv_bfloat16 th[64][66];
    __shared__ __nv_bfloat16 tl[64][66];
    const int bh = blockIdx.y;
    const int i0 = blockIdx.x * 64;
    const int tid = threadIdx.x;

    #pragma unroll
    for (int it = 0; it < 16; it++) {
        int idx = tid + it * 256;
        int t = idx >> 6, d = idx & 63;
        size_t src = ((size_t)bh * SEQ + i0 + t) * DK + d;
        th[t][d] = g_Vh[src];
        tl[t][d] = g_Vl[src];
    }
    __syncthreads();
    #pragma unroll
    for (int it = 0; it < 16; it++) {
        int idx = tid + it * 256;
        int d = idx >> 6, t = idx & 63;
        size_t dst = ((size_t)bh * DK + d) * SEQ + i0 + t;
        g_Vth[dst] = th[t][d];
        g_Vtl[dst] = tl[t][d];
    }
}

// ---------------------------------------------------------------------------
// flash_mma v2: 128-query CTA, 8 warps (256 thr), 2 CTAs/SM.
// Per-warp math identical to v1 (16 query rows each) -> same rel_err.
// ---------------------------------------------------------------------------
#define KP   144
#define FARR 9216     // 64 * KP
#define FBUF 36864    // 4 arrays (Kh, Kl, Vh, Vl)

__global__ __launch_bounds__(256, 2) void flash_mma()
{
    extern __shared__ char fsm[];
    const uint32_t fb = smem_to_u32(fsm);

    const int tid = threadIdx.x;
    const int w = tid >> 5, lane = tid & 31;   // w in [0,8)
    const int g = lane >> 2, q = lane & 3;
    const int bh = blockIdx.y;
    const int b = bh >> 4, h = bh & 15;
    const int i0 = blockIdx.x * 128;
    const int rloc = 16 * w + g;               // local query row in [0,128)

    const uint32_t bRow = (uint32_t)(((lane >> 4) & 1) * 8 + (lane & 7)) * KP +
                          ((lane >> 3) & 1) * 16;

    const __nv_bfloat16* gsrc[4] = {
        g_Kh  + (size_t)bh * SEQ * DK,
        g_Kl  + (size_t)bh * SEQ * DK,
        g_Vth + (size_t)bh * DK * SEQ,
        g_Vtl + (size_t)bh * DK * SEQ };

    auto issue_f = [&](int jt) {
        const uint32_t buf = fb + (jt & 1) * FBUF;
        const int j0 = jt * 64;
        #pragma unroll
        for (int a = 0; a < 4; a++) {
            const size_t rstride = (a < 2) ? DK : SEQ;
            const size_t off = (a < 2) ? (size_t)j0 * DK : (size_t)j0;
            #pragma unroll
            for (int i = 0; i < 2; i++) {
                int id = tid + i * 256;        // 0..511
                int row = id >> 3, c8 = id & 7;
                cp_async16(buf + a * FARR + row * KP + c8 * 16,
                           gsrc[a] + off + (size_t)row * rstride + c8 * 8);
            }
        }
        cp_commit();
    };

    uint32_t qh[4][4], ql[4][4];
    {
        const size_t base = ((size_t)bh * SEQ + i0 + rloc) * DK;
        #pragma unroll
        for (int ks = 0; ks < 4; ks++) {
            size_t e = base + ks * 16 + 2 * q;
            qh[ks][0] = *(const uint32_t*)(g_Qh + e);
            qh[ks][1] = *(const uint32_t*)(g_Qh + e + 8 * DK);
            qh[ks][2] = *(const uint32_t*)(g_Qh + e + 8);
            qh[ks][3] = *(const uint32_t*)(g_Qh + e + 8 * DK + 8);
            ql[ks][0] = *(const uint32_t*)(g_Ql + e);
            ql[ks][1] = *(const uint32_t*)(g_Ql + e + 8 * DK);
            ql[ks][2] = *(const uint32_t*)(g_Ql + e + 8);
            ql[ks][3] = *(const uint32_t*)(g_Ql + e + 8 * DK + 8);
        }
    }

    float o[8][4] = {};
    float m0 = -1e30f, m1 = -1e30f, l0 = 0.f, l1 = 0.f;

    const int ntiles = 2 * blockIdx.x + 2;     // 64-key tiles covering keys <= i0+127
    const int jlast = ntiles - 1;
    issue_f(0);
    #pragma unroll 1
    for (int jt = 0; jt < ntiles; jt++) {
        if (jt > 0) __syncthreads();           // all warps done reading buf[(jt+1)&1]
        if (jt < jlast) { issue_f(jt + 1); cp_wait<1>(); }
        else            { cp_wait<0>(); }
        __syncthreads();                       // buf[jt&1] complete + visible

        const uint32_t buf = fb + (jt & 1) * FBUF;
        const uint32_t kBaseH = buf + bRow;
        const uint32_t kBaseL = buf + FARR + bRow;
        const uint32_t vBaseH = buf + 2 * FARR + bRow;
        const uint32_t vBaseL = buf + 3 * FARR + bRow;

        // S = Qh*Kh + Qh*Kl + Ql*Kh
        float s[8][4];
        #pragma unroll
        for (int an = 0; an < 8; an++)
            s[an][0] = s[an][1] = s[an][2] = s[an][3] = 0.f;
        #pragma unroll
        for (int ks = 0; ks < 4; ks++) {
            #pragma unroll
            for (int j = 0; j < 4; j++) {
                uint32_t kh4[4], kl4[4];
                const uint32_t off = (uint32_t)j * 16 * KP + ks * 32;
                ldsm_x4(kh4, kBaseH + off);
                ldsm_x4(kl4, kBaseL + off);
                mma_bf16(s[2 * j],     qh[ks], &kh4[0]);
                mma_bf16(s[2 * j],     qh[ks], &kl4[0]);
                mma_bf16(s[2 * j],     ql[ks], &kh4[0]);
                mma_bf16(s[2 * j + 1], qh[ks], &kh4[2]);
                mma_bf16(s[2 * j + 1], qh[ks], &kl4[2]);
                mma_bf16(s[2 * j + 1], ql[ks], &kh4[2]);
            }
        }

        // causal mask: last two j-tiles overlap the diagonal of this 128-row block
        const int coff = jt * 64 - i0;         // >= 0 only for jt >= 2*blockIdx.x
        if (coff + 63 > 0) {                   // needMask
            #pragma unroll
            for (int an = 0; an < 8; an++) {
                int c0 = coff + an * 8 + 2 * q, c1 = c0 + 1;
                if (c0 > rloc)     s[an][0] = -1e9f;
                if (c1 > rloc)     s[an][1] = -1e9f;
                if (c0 > rloc + 8) s[an][2] = -1e9f;
                if (c1 > rloc + 8) s[an][3] = -1e9f;
            }
        }

        float mx0 = -1e30f, mx1 = -1e30f;
        #pragma unroll
        for (int an = 0; an < 8; an++) {
            mx0 = fmaxf(mx0, fmaxf(s[an][0], s[an][1]));
            mx1 = fmaxf(mx1, fmaxf(s[an][2], s[an][3]));
        }
        mx0 = fmaxf(mx0, __shfl_xor_sync(0xFFFFFFFF, mx0, 1));
        mx0 = fmaxf(mx0, __shfl_xor_sync(0xFFFFFFFF, mx0, 2));
        mx1 = fmaxf(mx1, __shfl_xor_sync(0xFFFFFFFF, mx1, 1));
        mx1 = fmaxf(mx1, __shfl_xor_sync(0xFFFFFFFF, mx1, 2));
        float mn0 = fmaxf(m0, mx0), mn1 = fmaxf(m1, mx1);
        float a0 = __expf(m0 - mn0), a1 = __expf(m1 - mn1);
        float sum0 = 0.f, sum1 = 0.f;
        #pragma unroll
        for (int an = 0; an < 8; an++) {
            s[an][0] = __expf(s[an][0] - mn0);
            s[an][1] = __expf(s[an][1] - mn0);
            s[an][2] = __expf(s[an][2] - mn1);
            s[an][3] = __expf(s[an][3] - mn1);
            sum0 += s[an][0] + s[an][1];
            sum1 += s[an][2] + s[an][3];
        }
        sum0 += __shfl_xor_sync(0xFFFFFFFF, sum0, 1);
        sum0 += __shfl_xor_sync(0xFFFFFFFF, sum0, 2);
        sum1 += __shfl_xor_sync(0xFFFFFFFF, sum1, 1);
        sum1 += __shfl_xor_sync(0xFFFFFFFF, sum1, 2);
        l0 = l0 * a0 + sum0;  l1 = l1 * a1 + sum1;
        m0 = mn0;  m1 = mn1;
        #pragma unroll
        for (int an = 0; an < 8; an++) {
            o[an][0] *= a0; o[an][1] *= a0;
            o[an][2] *= a1; o[an][3] *= a1;
        }

        uint32_t ph[4][4], pl[4][4];
        #pragma unroll
        for (int kb = 0; kb < 4; kb++) {
            split2(s[2 * kb][0],     s[2 * kb][1],     ph[kb][0], pl[kb][0]);
            split2(s[2 * kb][2],     s[2 * kb][3],     ph[kb][1], pl[kb][1]);
            split2(s[2 * kb + 1][0], s[2 * kb + 1][1], ph[kb][2], pl[kb][2]);
            split2(s[2 * kb + 1][2], s[2 * kb + 1][3], ph[kb][3], pl[kb][3]);
        }

        // O += Ph*Vh + Ph*Vl + Pl*Vh
        #pragma unroll
        for (int kb = 0; kb < 4; kb++) {
            #pragma unroll
            for (int j = 0; j < 4; j++) {
                uint32_t vh4[4], vl4[4];
                const uint32_t off = (uint32_t)j * 16 * KP + kb * 32;
                ldsm_x4(vh4, vBaseH + off);
                ldsm_x4(vl4, vBaseL + off);
                mma_bf16(o[2 * j],     ph[kb], &vh4[0]);
                mma_bf16(o[2 * j],     ph[kb], &vl4[0]);
                mma_bf16(o[2 * j],     pl[kb], &vh4[0]);
                mma_bf16(o[2 * j + 1], ph[kb], &vh4[2]);
                mma_bf16(o[2 * j + 1], ph[kb], &vl4[2]);
                mma_bf16(o[2 * j + 1], pl[kb], &vh4[2]);
            }
        }
    }

    const float li0 = 1.f / l0, li1 = 1.f / l1;
    const size_t row0 = (size_t)b * SEQ + i0 + rloc;
    #pragma unroll
    for (int an = 0; an < 8; an++) {
        const int col = h * DK + an * 8 + 2 * q;
        uint32_t hi, lo;
        split2(o[an][0] * li0, o[an][1] * li0, hi, lo);
        *(uint32_t*)(g_A_hi + row0 * D_MODEL + col) = hi;
        *(uint32_t*)(g_A_lo + row0 * D_MODEL + col) = lo;
        split2(o[an][2] * li1, o[an][3] * li1, hi, lo);
        *(uint32_t*)(g_A_hi + (row0 + 8) * D_MODEL + col) = hi;
        *(uint32_t*)(g_A_lo + (row0 + 8) * D_MODEL + col) = lo;
    }
}

// ---------------------------------------------------------------------------
extern "C" void kernel_launch(void* const* d_in, const int* in_sizes, int n_in,
                              void* d_out, int out_size)
{
    const float* x     = (const float*)d_in[0];
    const float* Wqkv  = (const float*)d_in[1];
    const float* Wproj = (const float*)d_in[2];
    float* out = (float*)d_out;

    const int GEMM_SMEM  = 2 * BUFSZ;   // 80 KB
    const int FLASH_SMEM = 2 * FBUF;    // 72 KB
    cudaFuncSetAttribute(mma_gemm<true>,
                         cudaFuncAttributeMaxDynamicSharedMemorySize, GEMM_SMEM);
    cudaFuncSetAttribute(mma_gemm<false>,
                         cudaFuncAttributeMaxDynamicSharedMemorySize, GEMM_SMEM);
    cudaFuncSetAttribute(flash_mma,
                         cudaFuncAttributeMaxDynamicSharedMemorySize, FLASH_SMEM);

    // weight prepasses
    wprep_kernel<0><<<dim3(3 * D_MODEL / 32, D_MODEL / 32), dim3(32, 8)>>>(Wqkv, 3 * D_MODEL);
    wprep_kernel<1><<<dim3(D_MODEL / 32, D_MODEL / 32), dim3(32, 8)>>>(Wproj, D_MODEL);

    // x -> hi/lo
    aprep_kernel<<<(size_t)MTOT * D_MODEL / 4 / 256, 256>>>(x);

    // qkv GEMM with fused split epilogue -> g_Qh/Ql, g_Kh/Kl, g_Vh/Vl
    mma_gemm<true><<<dim3(3 * D_MODEL / 128, MTOT / 128), 256, GEMM_SMEM>>>(nullptr);

    // V transpose for flash B-operand layout
    vtrans_kernel<<<dim3(SEQ / 64, BH), 256>>>();

    // tensor-core flash attention (128-query CTAs) -> writes g_A_hi/g_A_lo
    flash_mma<<<dim3(SEQ / 128, BH), 256, FLASH_SMEM>>>();

    // out = attn @ W_proj
    mma_gemm<false><<<dim3(D_MODEL / 128, MTOT / 128), 256, GEMM_SMEM>>>(out);
}

// round 16
// speedup vs baseline: 1.0215x; 1.0215x over previous
#include <cuda_runtime.h>
#include <cuda_bf16.h>
#include <cstdint>
#include <cstddef>

#define D_MODEL 1024
#define N_HEADS 16
#define DK      64
#define BATCH   4
#define SEQ     2048
#define MTOT    (BATCH * SEQ)     // 8192
#define BH      (BATCH * N_HEADS) // 64

// ---------------- device global scratch (no allocation APIs allowed) --------
__device__ __nv_bfloat16 g_A_hi[(size_t)MTOT * D_MODEL];         // GEMM A input (x, then attn)
__device__ __nv_bfloat16 g_A_lo[(size_t)MTOT * D_MODEL];
__device__ __nv_bfloat16 g_Wq_hi[(size_t)3 * D_MODEL * D_MODEL]; // [3072][1024] K-major
__device__ __nv_bfloat16 g_Wq_lo[(size_t)3 * D_MODEL * D_MODEL];
__device__ __nv_bfloat16 g_Wp_hi[(size_t)D_MODEL * D_MODEL];
__device__ __nv_bfloat16 g_Wp_lo[(size_t)D_MODEL * D_MODEL];
// flash operands, per (b,h) planar  (written directly by QKV GEMM epilogue)
__device__ __nv_bfloat16 g_Qh[(size_t)BH * SEQ * DK];            // [bh][t][64], pre-scaled
__device__ __nv_bfloat16 g_Ql[(size_t)BH * SEQ * DK];
__device__ __nv_bfloat16 g_Kh[(size_t)BH * SEQ * DK];
__device__ __nv_bfloat16 g_Kl[(size_t)BH * SEQ * DK];
__device__ __nv_bfloat16 g_Vh[(size_t)BH * SEQ * DK];            // [bh][t][64]
__device__ __nv_bfloat16 g_Vl[(size_t)BH * SEQ * DK];

// ---------------- arch-agnostic PTX helpers (sm_80+ only) ------------------
__device__ __forceinline__ uint32_t smem_to_u32(const void* p) {
    uint32_t a;
    asm("{ .reg .u64 t; cvta.to.shared.u64 t, %1; cvt.u32.u64 %0, t; }"
        : "=r"(a) : "l"(p));
    return a;
}
__device__ __forceinline__ void cp_async16(uint32_t dst, const void* src) {
    asm volatile("cp.async.cg.shared.global [%0], [%1], 16;\n" :: "r"(dst), "l"(src));
}
__device__ __forceinline__ void cp_commit() {
    asm volatile("cp.async.commit_group;\n" ::: "memory");
}
template <int N>
__device__ __forceinline__ void cp_wait() {
    asm volatile("cp.async.wait_group %0;\n" :: "n"(N) : "memory");
}
__device__ __forceinline__ void mma_bf16(float* d, const uint32_t* a, const uint32_t* b) {
    asm volatile(
        "mma.sync.aligned.m16n8k16.row.col.f32.bf16.bf16.f32 "
        "{%0,%1,%2,%3}, {%4,%5,%6,%7}, {%8,%9}, {%0,%1,%2,%3};\n"
        : "+f"(d[0]), "+f"(d[1]), "+f"(d[2]), "+f"(d[3])
        : "r"(a[0]), "r"(a[1]), "r"(a[2]), "r"(a[3]), "r"(b[0]), "r"(b[1]));
}
// ldmatrix x4: 4 fragment regs in one instruction (sm_75+)
__device__ __forceinline__ void ldsm_x4(uint32_t* r, uint32_t addr) {
    asm volatile("ldmatrix.sync.aligned.m8n8.x4.shared.b16 {%0,%1,%2,%3}, [%4];"
        : "=r"(r[0]), "=r"(r[1]), "=r"(r[2]), "=r"(r[3]) : "r"(addr));
}
// ldmatrix x4 transposed: loads [k][n]-stored tiles as B fragments
__device__ __forceinline__ void ldsm_x4_trans(uint32_t* r, uint32_t addr) {
    asm volatile("ldmatrix.sync.aligned.m8n8.x4.trans.shared.b16 {%0,%1,%2,%3}, [%4];"
        : "=r"(r[0]), "=r"(r[1]), "=r"(r[2]), "=r"(r[3]) : "r"(addr));
}
// split two fp32 into packed bf16x2 hi and lo-residual
__device__ __forceinline__ void split2(float x, float y, uint32_t& hi, uint32_t& lo) {
    __nv_bfloat16 hx = __float2bfloat16(x), hy = __float2bfloat16(y);
    __nv_bfloat16 lx = __float2bfloat16(x - __bfloat162float(hx));
    __nv_bfloat16 ly = __float2bfloat16(y - __bfloat162float(hy));
    __nv_bfloat162 hp(hx, hy), lp(lx, ly);
    hi = *(uint32_t*)&hp; lo = *(uint32_t*)&lp;
}

// ---------------------------------------------------------------------------
// Prepass: split fp32 x into bf16 hi/lo (GEMM A input).
// ---------------------------------------------------------------------------
__global__ __launch_bounds__(256) void aprep_kernel(const float* __restrict__ xin)
{
    size_t i = ((size_t)blockIdx.x * 256 + threadIdx.x) * 4;
    float4 v = *(const float4*)(xin + i);
    uint32_t h0, l0, h1, l1;
    split2(v.x, v.y, h0, l0);
    split2(v.z, v.w, h1, l1);
    *(uint2*)(g_A_hi + i) = make_uint2(h0, h1);
    *(uint2*)(g_A_lo + i) = make_uint2(l0, l1);
}

// ---------------------------------------------------------------------------
// Prepass: transpose W [1024][N] -> [N][1024] and split hi/lo.
// ---------------------------------------------------------------------------
template <int WHICH>
__global__ __launch_bounds__(256) void wprep_kernel(const float* __restrict__ W, int N)
{
    __shared__ float t[32][33];
    const int n0 = blockIdx.x * 32, k0 = blockIdx.y * 32;
    const int tx = threadIdx.x, ty = threadIdx.y;
    #pragma unroll
    for (int i = 0; i < 4; i++)
        t[ty + 8 * i][tx] = W[(size_t)(k0 + ty + 8 * i) * N + n0 + tx];
    __syncthreads();
    __nv_bfloat16* hi = (WHICH == 0) ? g_Wq_hi : g_Wp_hi;
    __nv_bfloat16* lo = (WHICH == 0) ? g_Wq_lo : g_Wp_lo;
    #pragma unroll
    for (int i = 0; i < 4; i++) {
        int n = n0 + ty + 8 * i, k = k0 + tx;
        float v = t[tx][ty + 8 * i];
        __nv_bfloat16 h = __float2bfloat16(v);
        hi[(size_t)n * D_MODEL + k] = h;
        lo[(size_t)n * D_MODEL + k] = __float2bfloat16(v - __bfloat162float(h));
    }
}

// ---------------------------------------------------------------------------
// bf16x3 GEMM via mma.sync.m16n8k16 + ldmatrix — ROUND-11 PROVEN VERSION
// (pitch 80, 2-buffer double buffering, 2 barriers/chunk, 2 CTAs/SM).
// IS_QKV: fused epilogue writes planar bf16 hi/lo Q (x0.125) / K / V directly.
// ---------------------------------------------------------------------------
#define GPITCH 80
#define TSZ    10240   // 128 rows * 80B
#define BUFSZ  40960   // 4 tensors

template <bool IS_QKV>
__global__ __launch_bounds__(256, 2) void mma_gemm(float* __restrict__ Cparam)
{
    extern __shared__ char smem[];
    const int N = IS_QKV ? 3 * D_MODEL : D_MODEL;
    const __nv_bfloat16* BhiG = IS_QKV ? g_Wq_hi : g_Wp_hi;
    const __nv_bfloat16* BloG = IS_QKV ? g_Wq_lo : g_Wp_lo;

    const int tid = threadIdx.x;
    const int wid = tid >> 5, lane = tid & 31;
    const int wm = wid & 3, wn = wid >> 2;
    const int g = lane >> 2, q = lane & 3;
    const int m0 = blockIdx.y * 128, n0 = blockIdx.x * 128;

    const char* srcs[4] = {
        (const char*)(g_A_hi + (size_t)m0 * D_MODEL),
        (const char*)(g_A_lo + (size_t)m0 * D_MODEL),
        (const char*)(BhiG + (size_t)n0 * D_MODEL),
        (const char*)(BloG + (size_t)n0 * D_MODEL) };

    const uint32_t sb = smem_to_u32(smem);

    const uint32_t aOff = (uint32_t)(wm * 32 + (lane & 15)) * GPITCH + (lane >> 4) * 16;
    const uint32_t bOff = 2 * TSZ +
        (uint32_t)(wn * 64 + ((lane >> 4) & 1) * 8 + (lane & 7)) * GPITCH +
        ((lane >> 3) & 1) * 16;

    float acc[2][8][4] = {};

    auto issue = [&](int c) {
        const uint32_t buf = sb + (c & 1) * BUFSZ;
        const size_t koff = (size_t)c * 64;
        #pragma unroll
        for (int i = 0; i < 8; i++) {
            int id = tid + i * 256;
            int t = id >> 9;
            int rem = id & 511;
            int row = rem >> 2, c16 = rem & 3;
            cp_async16(buf + t * TSZ + row * GPITCH + c16 * 16,
                       srcs[t] + (size_t)row * 2048 + koff + c16 * 16);
        }
        cp_commit();
    };

    issue(0);
    #pragma unroll 1
    for (int c = 0; c < 32; c++) {
        if (c + 1 < 32) { issue(c + 1); cp_wait<1>(); }
        else            { cp_wait<0>(); }
        __syncthreads();

        const uint32_t buf = sb + (c & 1) * BUFSZ;
        #pragma unroll
        for (int ks = 0; ks < 2; ks++) {
            const uint32_t ksb = ks * 32;
            uint32_t ah[2][4], al[2][4], bh[4][4], bl[4][4];
            #pragma unroll
            for (int am = 0; am < 2; am++) {
                const uint32_t a = buf + aOff + (uint32_t)am * 16 * GPITCH + ksb;
                ldsm_x4(ah[am], a);
                ldsm_x4(al[am], a + TSZ);
            }
            #pragma unroll
            for (int j = 0; j < 4; j++) {
                const uint32_t a = buf + bOff + (uint32_t)j * 16 * GPITCH + ksb;
                ldsm_x4(bh[j], a);
                ldsm_x4(bl[j], a + TSZ);
            }
            #pragma unroll
            for (int am = 0; am < 2; am++)
                #pragma unroll
                for (int j = 0; j < 4; j++) {
                    mma_bf16(acc[am][2 * j],     ah[am], &bh[j][0]);
                    mma_bf16(acc[am][2 * j],     ah[am], &bl[j][0]);
                    mma_bf16(acc[am][2 * j],     al[am], &bh[j][0]);
                    mma_bf16(acc[am][2 * j + 1], ah[am], &bh[j][2]);
                    mma_bf16(acc[am][2 * j + 1], ah[am], &bl[j][2]);
                    mma_bf16(acc[am][2 * j + 1], al[am], &bh[j][2]);
                }
        }
        __syncthreads();
    }

    if (IS_QKV) {
        // fused epilogue: split hi/lo, write planar [bh][t][64]
        const int region = n0 >> 10;                         // 0=Q, 1=K, 2=V
        __nv_bfloat16* dsthi = (region == 0) ? g_Qh : (region == 1) ? g_Kh : g_Vh;
        __nv_bfloat16* dstlo = (region == 0) ? g_Ql : (region == 1) ? g_Kl : g_Vl;
        const float scale = (region == 0) ? 0.125f : 1.0f;
        const int crbase = (n0 & 1023) + wn * 64;
        const int b = m0 >> 11;                              // batch (tiles don't span)
        #pragma unroll
        for (int am = 0; am < 2; am++) {
            const int t0 = (m0 & 2047) + wm * 32 + am * 16 + g;
            #pragma unroll
            for (int an = 0; an < 8; an++) {
                const int cr = crbase + an * 8 + q * 2;
                const int h = cr >> 6, d = cr & 63;
                const size_t base = (((size_t)(b * 16 + h)) * SEQ + t0) * DK + d;
                uint32_t hi, lo;
                split2(acc[am][an][0] * scale, acc[am][an][1] * scale, hi, lo);
                *(uint32_t*)(dsthi + base) = hi;
                *(uint32_t*)(dstlo + base) = lo;
                split2(acc[am][an][2] * scale, acc[am][an][3] * scale, hi, lo);
                *(uint32_t*)(dsthi + base + 8 * DK) = hi;
                *(uint32_t*)(dstlo + base + 8 * DK) = lo;
            }
        }
    } else {
        #pragma unroll
        for (int am = 0; am < 2; am++) {
            const int row = m0 + wm * 32 + am * 16 + g;
            #pragma unroll
            for (int an = 0; an < 8; an++) {
                const int col = n0 + wn * 64 + an * 8 + q * 2;
                *(float2*)(Cparam + (size_t)row * N + col) =
                    make_float2(acc[am][an][0], acc[am][an][1]);
                *(float2*)(Cparam + (size_t)(row + 8) * N + col) =
                    make_float2(acc[am][an][2], acc[am][an][3]);
            }
        }
    }
}

// ---------------------------------------------------------------------------
// flash_mma: round-11 v1 (64-query CTA, 128 threads) with V loaded directly
// from [t][64] layout via ldmatrix.trans — vtrans kernel eliminated.
// ---------------------------------------------------------------------------
#define KP   144
#define FARR 9216     // 64 * KP
#define FBUF 36864    // 4 arrays (Kh, Kl, Vh, Vl)

__global__ __launch_bounds__(128) void flash_mma()
{
    extern __shared__ char fsm[];
    const uint32_t fb = smem_to_u32(fsm);

    const int tid = threadIdx.x;
    const int w = tid >> 5, lane = tid & 31;
    const int g = lane >> 2, q = lane & 3;
    const int bh = blockIdx.y;
    const int b = bh >> 4, h = bh & 15;
    const int i0 = blockIdx.x * 64;
    const int rloc = 16 * w + g;

    // K fragments (non-trans): row = n(key), col16 = k-half
    const uint32_t bRow = (uint32_t)(((lane >> 4) & 1) * 8 + (lane & 7)) * KP +
                          ((lane >> 3) & 1) * 16;
    // V fragments (trans): row = t(key index), col16 = d-half
    const uint32_t vRow = (uint32_t)(((lane >> 3) & 1) * 8 + (lane & 7)) * KP +
                          ((lane >> 4) & 1) * 16;

    const __nv_bfloat16* gsrc[4] = {
        g_Kh + (size_t)bh * SEQ * DK,
        g_Kl + (size_t)bh * SEQ * DK,
        g_Vh + (size_t)bh * SEQ * DK,
        g_Vl + (size_t)bh * SEQ * DK };

    auto issue_f = [&](int jt) {
        const uint32_t buf = fb + (jt & 1) * FBUF;
        const int j0 = jt * 64;
        #pragma unroll
        for (int a = 0; a < 4; a++) {
            #pragma unroll
            for (int i = 0; i < 4; i++) {
                int id = tid + i * 128;
                int row = id >> 3, c8 = id & 7;
                cp_async16(buf + a * FARR + row * KP + c8 * 16,
                           gsrc[a] + (size_t)(j0 + row) * DK + c8 * 8);
            }
        }
        cp_commit();
    };

    uint32_t qh[4][4], ql[4][4];
    {
        const size_t base = ((size_t)bh * SEQ + i0 + rloc) * DK;
        #pragma unroll
        for (int ks = 0; ks < 4; ks++) {
            size_t e = base + ks * 16 + 2 * q;
            qh[ks][0] = *(const uint32_t*)(g_Qh + e);
            qh[ks][1] = *(const uint32_t*)(g_Qh + e + 8 * DK);
            qh[ks][2] = *(const uint32_t*)(g_Qh + e + 8);
            qh[ks][3] = *(const uint32_t*)(g_Qh + e + 8 * DK + 8);
            ql[ks][0] = *(const uint32_t*)(g_Ql + e);
            ql[ks][1] = *(const uint32_t*)(g_Ql + e + 8 * DK);
            ql[ks][2] = *(const uint32_t*)(g_Ql + e + 8);
            ql[ks][3] = *(const uint32_t*)(g_Ql + e + 8 * DK + 8);
        }
    }

    float o[8][4] = {};
    float m0 = -1e30f, m1 = -1e30f, l0 = 0.f, l1 = 0.f;

    const int jmax = blockIdx.x;
    issue_f(0);
    #pragma unroll 1
    for (int jt = 0; jt <= jmax; jt++) {
        if (jt > 0) __syncthreads();
        if (jt < jmax) { issue_f(jt + 1); cp_wait<1>(); }
        else           { cp_wait<0>(); }
        __syncthreads();

        const uint32_t buf = fb + (jt & 1) * FBUF;
        const uint32_t kBaseH = buf + bRow;
        const uint32_t kBaseL = buf + FARR + bRow;
        const uint32_t vBaseH = buf + 2 * FARR + vRow;
        const uint32_t vBaseL = buf + 3 * FARR + vRow;

        // S = Qh*Kh + Qh*Kl + Ql*Kh
        float s[8][4];
        #pragma unroll
        for (int an = 0; an < 8; an++)
            s[an][0] = s[an][1] = s[an][2] = s[an][3] = 0.f;
        #pragma unroll
        for (int ks = 0; ks < 4; ks++) {
            #pragma unroll
            for (int j = 0; j < 4; j++) {
                uint32_t kh4[4], kl4[4];
                const uint32_t off = (uint32_t)j * 16 * KP + ks * 32;
                ldsm_x4(kh4, kBaseH + off);
                ldsm_x4(kl4, kBaseL + off);
                mma_bf16(s[2 * j],     qh[ks], &kh4[0]);
                mma_bf16(s[2 * j],     qh[ks], &kl4[0]);
                mma_bf16(s[2 * j],     ql[ks], &kh4[0]);
                mma_bf16(s[2 * j + 1], qh[ks], &kh4[2]);
                mma_bf16(s[2 * j + 1], qh[ks], &kl4[2]);
                mma_bf16(s[2 * j + 1], ql[ks], &kh4[2]);
            }
        }

        if (jt == jmax) {
            #pragma unroll
            for (int an = 0; an < 8; an++) {
                int c0 = an * 8 + 2 * q, c1 = c0 + 1;
                if (c0 > rloc)     s[an][0] = -1e9f;
                if (c1 > rloc)     s[an][1] = -1e9f;
                if (c0 > rloc + 8) s[an][2] = -1e9f;
                if (c1 > rloc + 8) s[an][3] = -1e9f;
            }
        }

        float mx0 = -1e30f, mx1 = -1e30f;
        #pragma unroll
        for (int an = 0; an < 8; an++) {
            mx0 = fmaxf(mx0, fmaxf(s[an][0], s[an][1]));
            mx1 = fmaxf(mx1, fmaxf(s[an][2], s[an][3]));
        }
        mx0 = fmaxf(mx0, __shfl_xor_sync(0xFFFFFFFF, mx0, 1));
        mx0 = fmaxf(mx0, __shfl_xor_sync(0xFFFFFFFF, mx0, 2));
        mx1 = fmaxf(mx1, __shfl_xor_sync(0xFFFFFFFF, mx1, 1));
        mx1 = fmaxf(mx1, __shfl_xor_sync(0xFFFFFFFF, mx1, 2));
        float mn0 = fmaxf(m0, mx0), mn1 = fmaxf(m1, mx1);
        float a0 = __expf(m0 - mn0), a1 = __expf(m1 - mn1);
        float sum0 = 0.f, sum1 = 0.f;
        #pragma unroll
        for (int an = 0; an < 8; an++) {
            s[an][0] = __expf(s[an][0] - mn0);
            s[an][1] = __expf(s[an][1] - mn0);
            s[an][2] = __expf(s[an][2] - mn1);
            s[an][3] = __expf(s[an][3] - mn1);
            sum0 += s[an][0] + s[an][1];
            sum1 += s[an][2] + s[an][3];
        }
        sum0 += __shfl_xor_sync(0xFFFFFFFF, sum0, 1);
        sum0 += __shfl_xor_sync(0xFFFFFFFF, sum0, 2);
        sum1 += __shfl_xor_sync(0xFFFFFFFF, sum1, 1);
        sum1 += __shfl_xor_sync(0xFFFFFFFF, sum1, 2);
        l0 = l0 * a0 + sum0;  l1 = l1 * a1 + sum1;
        m0 = mn0;  m1 = mn1;
        #pragma unroll
        for (int an = 0; an < 8; an++) {
            o[an][0] *= a0; o[an][1] *= a0;
            o[an][2] *= a1; o[an][3] *= a1;
        }

        uint32_t ph[4][4], pl[4][4];
        #pragma unroll
        for (int kb = 0; kb < 4; kb++) {
            split2(s[2 * kb][0],     s[2 * kb][1],     ph[kb][0], pl[kb][0]);
            split2(s[2 * kb][2],     s[2 * kb][3],     ph[kb][1], pl[kb][1]);
            split2(s[2 * kb + 1][0], s[2 * kb + 1][1], ph[kb][2], pl[kb][2]);
            split2(s[2 * kb + 1][2], s[2 * kb + 1][3], ph[kb][3], pl[kb][3]);
        }

        // O += Ph*Vh + Ph*Vl + Pl*Vh  (V via ldmatrix.trans from [t][64])
        #pragma unroll
        for (int kb = 0; kb < 4; kb++) {
            #pragma unroll
            for (int j = 0; j < 4; j++) {
                uint32_t vh4[4], vl4[4];
                const uint32_t off = (uint32_t)kb * 16 * KP + j * 32;
                ldsm_x4_trans(vh4, vBaseH + off);
                ldsm_x4_trans(vl4, vBaseL + off);
                mma_bf16(o[2 * j],     ph[kb], &vh4[0]);
                mma_bf16(o[2 * j],     ph[kb], &vl4[0]);
                mma_bf16(o[2 * j],     pl[kb], &vh4[0]);
                mma_bf16(o[2 * j + 1], ph[kb], &vh4[2]);
                mma_bf16(o[2 * j + 1], ph[kb], &vl4[2]);
                mma_bf16(o[2 * j + 1], pl[kb], &vh4[2]);
            }
        }
    }

    const float li0 = 1.f / l0, li1 = 1.f / l1;
    const size_t row0 = (size_t)b * SEQ + i0 + rloc;
    #pragma unroll
    for (int an = 0; an < 8; an++) {
        const int col = h * DK + an * 8 + 2 * q;
        uint32_t hi, lo;
        split2(o[an][0] * li0, o[an][1] * li0, hi, lo);
        *(uint32_t*)(g_A_hi + row0 * D_MODEL + col) = hi;
        *(uint32_t*)(g_A_lo + row0 * D_MODEL + col) = lo;
        split2(o[an][2] * li1, o[an][3] * li1, hi, lo);
        *(uint32_t*)(g_A_hi + (row0 + 8) * D_MODEL + col) = hi;
        *(uint32_t*)(g_A_lo + (row0 + 8) * D_MODEL + col) = lo;
    }
}

// ---------------------------------------------------------------------------
extern "C" void kernel_launch(void* const* d_in, const int* in_sizes, int n_in,
                              void* d_out, int out_size)
{
    const float* x     = (const float*)d_in[0];
    const float* Wqkv  = (const float*)d_in[1];
    const float* Wproj = (const float*)d_in[2];
    float* out = (float*)d_out;

    const int GEMM_SMEM  = 2 * BUFSZ;   // 80 KB
    const int FLASH_SMEM = 2 * FBUF;    // 72 KB
    cudaFuncSetAttribute(mma_gemm<true>,
                         cudaFuncAttributeMaxDynamicSharedMemorySize, GEMM_SMEM);
    cudaFuncSetAttribute(mma_gemm<false>,
                         cudaFuncAttributeMaxDynamicSharedMemorySize, GEMM_SMEM);
    cudaFuncSetAttribute(flash_mma,
                         cudaFuncAttributeMaxDynamicSharedMemorySize, FLASH_SMEM);

    // weight prepasses
    wprep_kernel<0><<<dim3(3 * D_MODEL / 32, D_MODEL / 32), dim3(32, 8)>>>(Wqkv, 3 * D_MODEL);
    wprep_kernel<1><<<dim3(D_MODEL / 32, D_MODEL / 32), dim3(32, 8)>>>(Wproj, D_MODEL);

    // x -> hi/lo
    aprep_kernel<<<(size_t)MTOT * D_MODEL / 4 / 256, 256>>>(x);

    // qkv GEMM with fused split epilogue -> g_Qh/Ql, g_Kh/Kl, g_Vh/Vl
    mma_gemm<true><<<dim3(3 * D_MODEL / 128, MTOT / 128), 256, GEMM_SMEM>>>(nullptr);

    // tensor-core flash attention (V loaded via ldmatrix.trans; no vtrans pass)
    flash_mma<<<dim3(SEQ / 64, BH), 128, FLASH_SMEM>>>();

    // out = attn @ W_proj
    mma_gemm<false><<<dim3(D_MODEL / 128, MTOT / 128), 256, GEMM_SMEM>>>(out);
}

// round 17
// speedup vs baseline: 1.0440x; 1.0220x over previous
#include <cuda_runtime.h>
#include <cuda_bf16.h>
#include <cstdint>
#include <cstddef>

#define D_MODEL 1024
#define N_HEADS 16
#define DK      64
#define BATCH   4
#define SEQ     2048
#define MTOT    (BATCH * SEQ)     // 8192
#define BH      (BATCH * N_HEADS) // 64

// ---------------- device global scratch (no allocation APIs allowed) --------
__device__ __nv_bfloat16 g_A_hi[(size_t)MTOT * D_MODEL];         // GEMM A input (x, then attn)
__device__ __nv_bfloat16 g_A_lo[(size_t)MTOT * D_MODEL];
__device__ __nv_bfloat16 g_Wq_hi[(size_t)3 * D_MODEL * D_MODEL]; // [3072][1024] K-major
__device__ __nv_bfloat16 g_Wq_lo[(size_t)3 * D_MODEL * D_MODEL];
__device__ __nv_bfloat16 g_Wp_hi[(size_t)D_MODEL * D_MODEL];
__device__ __nv_bfloat16 g_Wp_lo[(size_t)D_MODEL * D_MODEL];
// flash operands, per (b,h) planar  (written directly by QKV GEMM epilogue)
__device__ __nv_bfloat16 g_Qh[(size_t)BH * SEQ * DK];            // [bh][t][64], pre-scaled
__device__ __nv_bfloat16 g_Ql[(size_t)BH * SEQ * DK];
__device__ __nv_bfloat16 g_Kh[(size_t)BH * SEQ * DK];
__device__ __nv_bfloat16 g_Kl[(size_t)BH * SEQ * DK];
__device__ __nv_bfloat16 g_Vh[(size_t)BH * SEQ * DK];            // [bh][t][64]
__device__ __nv_bfloat16 g_Vl[(size_t)BH * SEQ * DK];

// ---------------- arch-agnostic PTX helpers (sm_80+ only) ------------------
__device__ __forceinline__ uint32_t smem_to_u32(const void* p) {
    uint32_t a;
    asm("{ .reg .u64 t; cvta.to.shared.u64 t, %1; cvt.u32.u64 %0, t; }"
        : "=r"(a) : "l"(p));
    return a;
}
__device__ __forceinline__ void cp_async16(uint32_t dst, const void* src) {
    asm volatile("cp.async.cg.shared.global [%0], [%1], 16;\n" :: "r"(dst), "l"(src));
}
__device__ __forceinline__ void cp_commit() {
    asm volatile("cp.async.commit_group;\n" ::: "memory");
}
template <int N>
__device__ __forceinline__ void cp_wait() {
    asm volatile("cp.async.wait_group %0;\n" :: "n"(N) : "memory");
}
__device__ __forceinline__ void mma_bf16(float* d, const uint32_t* a, const uint32_t* b) {
    asm volatile(
        "mma.sync.aligned.m16n8k16.row.col.f32.bf16.bf16.f32 "
        "{%0,%1,%2,%3}, {%4,%5,%6,%7}, {%8,%9}, {%0,%1,%2,%3};\n"
        : "+f"(d[0]), "+f"(d[1]), "+f"(d[2]), "+f"(d[3])
        : "r"(a[0]), "r"(a[1]), "r"(a[2]), "r"(a[3]), "r"(b[0]), "r"(b[1]));
}
// ldmatrix x4: 4 fragment regs in one instruction (sm_75+)
__device__ __forceinline__ void ldsm_x4(uint32_t* r, uint32_t addr) {
    asm volatile("ldmatrix.sync.aligned.m8n8.x4.shared.b16 {%0,%1,%2,%3}, [%4];"
        : "=r"(r[0]), "=r"(r[1]), "=r"(r[2]), "=r"(r[3]) : "r"(addr));
}
// ldmatrix x4 transposed: loads [k][n]-stored tiles as B fragments
__device__ __forceinline__ void ldsm_x4_trans(uint32_t* r, uint32_t addr) {
    asm volatile("ldmatrix.sync.aligned.m8n8.x4.trans.shared.b16 {%0,%1,%2,%3}, [%4];"
        : "=r"(r[0]), "=r"(r[1]), "=r"(r[2]), "=r"(r[3]) : "r"(addr));
}
// split two fp32 into packed bf16x2 hi and lo-residual
__device__ __forceinline__ void split2(float x, float y, uint32_t& hi, uint32_t& lo) {
    __nv_bfloat16 hx = __float2bfloat16(x), hy = __float2bfloat16(y);
    __nv_bfloat16 lx = __float2bfloat16(x - __bfloat162float(hx));
    __nv_bfloat16 ly = __float2bfloat16(y - __bfloat162float(hy));
    __nv_bfloat162 hp(hx, hy), lp(lx, ly);
    hi = *(uint32_t*)&hp; lo = *(uint32_t*)&lp;
}

// ---------------------------------------------------------------------------
// Prepass: split fp32 x into bf16 hi/lo (GEMM A input).
// ---------------------------------------------------------------------------
__global__ __launch_bounds__(256) void aprep_kernel(const float* __restrict__ xin)
{
    size_t i = ((size_t)blockIdx.x * 256 + threadIdx.x) * 4;
    float4 v = *(const float4*)(xin + i);
    uint32_t h0, l0, h1, l1;
    split2(v.x, v.y, h0, l0);
    split2(v.z, v.w, h1, l1);
    *(uint2*)(g_A_hi + i) = make_uint2(h0, h1);
    *(uint2*)(g_A_lo + i) = make_uint2(l0, l1);
}

// ---------------------------------------------------------------------------
// Prepass: transpose W [1024][N] -> [N][1024] and split hi/lo.
// ---------------------------------------------------------------------------
template <int WHICH>
__global__ __launch_bounds__(256) void wprep_kernel(const float* __restrict__ W, int N)
{
    __shared__ float t[32][33];
    const int n0 = blockIdx.x * 32, k0 = blockIdx.y * 32;
    const int tx = threadIdx.x, ty = threadIdx.y;
    #pragma unroll
    for (int i = 0; i < 4; i++)
        t[ty + 8 * i][tx] = W[(size_t)(k0 + ty + 8 * i) * N + n0 + tx];
    __syncthreads();
    __nv_bfloat16* hi = (WHICH == 0) ? g_Wq_hi : g_Wp_hi;
    __nv_bfloat16* lo = (WHICH == 0) ? g_Wq_lo : g_Wp_lo;
    #pragma unroll
    for (int i = 0; i < 4; i++) {
        int n = n0 + ty + 8 * i, k = k0 + tx;
        float v = t[tx][ty + 8 * i];
        __nv_bfloat16 h = __float2bfloat16(v);
        hi[(size_t)n * D_MODEL + k] = h;
        lo[(size_t)n * D_MODEL + k] = __float2bfloat16(v - __bfloat162float(h));
    }
}

// ---------------------------------------------------------------------------
// bf16x3 GEMM via mma.sync.m16n8k16 + ldmatrix — PROVEN VERSION (unchanged).
// IS_QKV: fused epilogue writes planar bf16 hi/lo Q (x0.125) / K / V directly.
// ---------------------------------------------------------------------------
#define GPITCH 80
#define TSZ    10240   // 128 rows * 80B
#define BUFSZ  40960   // 4 tensors

template <bool IS_QKV>
__global__ __launch_bounds__(256, 2) void mma_gemm(float* __restrict__ Cparam)
{
    extern __shared__ char smem[];
    const int N = IS_QKV ? 3 * D_MODEL : D_MODEL;
    const __nv_bfloat16* BhiG = IS_QKV ? g_Wq_hi : g_Wp_hi;
    const __nv_bfloat16* BloG = IS_QKV ? g_Wq_lo : g_Wp_lo;

    const int tid = threadIdx.x;
    const int wid = tid >> 5, lane = tid & 31;
    const int wm = wid & 3, wn = wid >> 2;
    const int g = lane >> 2, q = lane & 3;
    const int m0 = blockIdx.y * 128, n0 = blockIdx.x * 128;

    const char* srcs[4] = {
        (const char*)(g_A_hi + (size_t)m0 * D_MODEL),
        (const char*)(g_A_lo + (size_t)m0 * D_MODEL),
        (const char*)(BhiG + (size_t)n0 * D_MODEL),
        (const char*)(BloG + (size_t)n0 * D_MODEL) };

    const uint32_t sb = smem_to_u32(smem);

    const uint32_t aOff = (uint32_t)(wm * 32 + (lane & 15)) * GPITCH + (lane >> 4) * 16;
    const uint32_t bOff = 2 * TSZ +
        (uint32_t)(wn * 64 + ((lane >> 4) & 1) * 8 + (lane & 7)) * GPITCH +
        ((lane >> 3) & 1) * 16;

    float acc[2][8][4] = {};

    auto issue = [&](int c) {
        const uint32_t buf = sb + (c & 1) * BUFSZ;
        const size_t koff = (size_t)c * 64;
        #pragma unroll
        for (int i = 0; i < 8; i++) {
            int id = tid + i * 256;
            int t = id >> 9;
            int rem = id & 511;
            int row = rem >> 2, c16 = rem & 3;
            cp_async16(buf + t * TSZ + row * GPITCH + c16 * 16,
                       srcs[t] + (size_t)row * 2048 + koff + c16 * 16);
        }
        cp_commit();
    };

    issue(0);
    #pragma unroll 1
    for (int c = 0; c < 32; c++) {
        if (c + 1 < 32) { issue(c + 1); cp_wait<1>(); }
        else            { cp_wait<0>(); }
        __syncthreads();

        const uint32_t buf = sb + (c & 1) * BUFSZ;
        #pragma unroll
        for (int ks = 0; ks < 2; ks++) {
            const uint32_t ksb = ks * 32;
            uint32_t ah[2][4], al[2][4], bh[4][4], bl[4][4];
            #pragma unroll
            for (int am = 0; am < 2; am++) {
                const uint32_t a = buf + aOff + (uint32_t)am * 16 * GPITCH + ksb;
                ldsm_x4(ah[am], a);
                ldsm_x4(al[am], a + TSZ);
            }
            #pragma unroll
            for (int j = 0; j < 4; j++) {
                const uint32_t a = buf + bOff + (uint32_t)j * 16 * GPITCH + ksb;
                ldsm_x4(bh[j], a);
                ldsm_x4(bl[j], a + TSZ);
            }
            #pragma unroll
            for (int am = 0; am < 2; am++)
                #pragma unroll
                for (int j = 0; j < 4; j++) {
                    mma_bf16(acc[am][2 * j],     ah[am], &bh[j][0]);
                    mma_bf16(acc[am][2 * j],     ah[am], &bl[j][0]);
                    mma_bf16(acc[am][2 * j],     al[am], &bh[j][0]);
                    mma_bf16(acc[am][2 * j + 1], ah[am], &bh[j][2]);
                    mma_bf16(acc[am][2 * j + 1], ah[am], &bl[j][2]);
                    mma_bf16(acc[am][2 * j + 1], al[am], &bh[j][2]);
                }
        }
        __syncthreads();
    }

    if (IS_QKV) {
        // fused epilogue: split hi/lo, write planar [bh][t][64]
        const int region = n0 >> 10;                         // 0=Q, 1=K, 2=V
        __nv_bfloat16* dsthi = (region == 0) ? g_Qh : (region == 1) ? g_Kh : g_Vh;
        __nv_bfloat16* dstlo = (region == 0) ? g_Ql : (region == 1) ? g_Kl : g_Vl;
        const float scale = (region == 0) ? 0.125f : 1.0f;
        const int crbase = (n0 & 1023) + wn * 64;
        const int b = m0 >> 11;                              // batch (tiles don't span)
        #pragma unroll
        for (int am = 0; am < 2; am++) {
            const int t0 = (m0 & 2047) + wm * 32 + am * 16 + g;
            #pragma unroll
            for (int an = 0; an < 8; an++) {
                const int cr = crbase + an * 8 + q * 2;
                const int h = cr >> 6, d = cr & 63;
                const size_t base = (((size_t)(b * 16 + h)) * SEQ + t0) * DK + d;
                uint32_t hi, lo;
                split2(acc[am][an][0] * scale, acc[am][an][1] * scale, hi, lo);
                *(uint32_t*)(dsthi + base) = hi;
                *(uint32_t*)(dstlo + base) = lo;
                split2(acc[am][an][2] * scale, acc[am][an][3] * scale, hi, lo);
                *(uint32_t*)(dsthi + base + 8 * DK) = hi;
                *(uint32_t*)(dstlo + base + 8 * DK) = lo;
            }
        }
    } else {
        #pragma unroll
        for (int am = 0; am < 2; am++) {
            const int row = m0 + wm * 32 + am * 16 + g;
            #pragma unroll
            for (int an = 0; an < 8; an++) {
                const int col = n0 + wn * 64 + an * 8 + q * 2;
                *(float2*)(Cparam + (size_t)row * N + col) =
                    make_float2(acc[am][an][0], acc[am][an][1]);
                *(float2*)(Cparam + (size_t)(row + 8) * N + col) =
                    make_float2(acc[am][an][2], acc[am][an][3]);
            }
        }
    }
}

// ---------------------------------------------------------------------------
// flash_mma: 64-query CTA, 128 threads, V via ldmatrix.trans.
// ROUND 17: (a) reversed CTA->tile mapping (longest CTAs first, kills the
// causal-triangle tail); (b) __launch_bounds__(128,3): 3 CTAs/SM
// (216KB smem, reg cap 170 — above flash's ~150 live regs).
// ---------------------------------------------------------------------------
#define KP   144
#define FARR 9216     // 64 * KP
#define FBUF 36864    // 4 arrays (Kh, Kl, Vh, Vl)

__global__ __launch_bounds__(128, 3) void flash_mma()
{
    extern __shared__ char fsm[];
    const uint32_t fb = smem_to_u32(fsm);

    const int tid = threadIdx.x;
    const int w = tid >> 5, lane = tid & 31;
    const int g = lane >> 2, q = lane & 3;
    const int bh = blockIdx.y;
    const int b = bh >> 4, h = bh & 15;
    const int qi = gridDim.x - 1 - blockIdx.x;   // longest CTAs scheduled first
    const int i0 = qi * 64;
    const int rloc = 16 * w + g;

    // K fragments (non-trans): row = n(key), col16 = k-half
    const uint32_t bRow = (uint32_t)(((lane >> 4) & 1) * 8 + (lane & 7)) * KP +
                          ((lane >> 3) & 1) * 16;
    // V fragments (trans): row = t(key index), col16 = d-half
    const uint32_t vRow = (uint32_t)(((lane >> 3) & 1) * 8 + (lane & 7)) * KP +
                          ((lane >> 4) & 1) * 16;

    const __nv_bfloat16* gsrc[4] = {
        g_Kh + (size_t)bh * SEQ * DK,
        g_Kl + (size_t)bh * SEQ * DK,
        g_Vh + (size_t)bh * SEQ * DK,
        g_Vl + (size_t)bh * SEQ * DK };

    auto issue_f = [&](int jt) {
        const uint32_t buf = fb + (jt & 1) * FBUF;
        const int j0 = jt * 64;
        #pragma unroll
        for (int a = 0; a < 4; a++) {
            #pragma unroll
            for (int i = 0; i < 4; i++) {
                int id = tid + i * 128;
                int row = id >> 3, c8 = id & 7;
                cp_async16(buf + a * FARR + row * KP + c8 * 16,
                           gsrc[a] + (size_t)(j0 + row) * DK + c8 * 8);
            }
        }
        cp_commit();
    };

    uint32_t qh[4][4], ql[4][4];
    {
        const size_t base = ((size_t)bh * SEQ + i0 + rloc) * DK;
        #pragma unroll
        for (int ks = 0; ks < 4; ks++) {
            size_t e = base + ks * 16 + 2 * q;
            qh[ks][0] = *(const uint32_t*)(g_Qh + e);
            qh[ks][1] = *(const uint32_t*)(g_Qh + e + 8 * DK);
            qh[ks][2] = *(const uint32_t*)(g_Qh + e + 8);
            qh[ks][3] = *(const uint32_t*)(g_Qh + e + 8 * DK + 8);
            ql[ks][0] = *(const uint32_t*)(g_Ql + e);
            ql[ks][1] = *(const uint32_t*)(g_Ql + e + 8 * DK);
            ql[ks][2] = *(const uint32_t*)(g_Ql + e + 8);
            ql[ks][3] = *(const uint32_t*)(g_Ql + e + 8 * DK + 8);
        }
    }

    float o[8][4] = {};
    float m0 = -1e30f, m1 = -1e30f, l0 = 0.f, l1 = 0.f;

    const int jmax = qi;
    issue_f(0);
    #pragma unroll 1
    for (int jt = 0; jt <= jmax; jt++) {
        if (jt > 0) __syncthreads();
        if (jt < jmax) { issue_f(jt + 1); cp_wait<1>(); }
        else           { cp_wait<0>(); }
        __syncthreads();

        const uint32_t buf = fb + (jt & 1) * FBUF;
        const uint32_t kBaseH = buf + bRow;
        const uint32_t kBaseL = buf + FARR + bRow;
        const uint32_t vBaseH = buf + 2 * FARR + vRow;
        const uint32_t vBaseL = buf + 3 * FARR + vRow;

        // S = Qh*Kh + Qh*Kl + Ql*Kh
        float s[8][4];
        #pragma unroll
        for (int an = 0; an < 8; an++)
            s[an][0] = s[an][1] = s[an][2] = s[an][3] = 0.f;
        #pragma unroll
        for (int ks = 0; ks < 4; ks++) {
            #pragma unroll
            for (int j = 0; j < 4; j++) {
                uint32_t kh4[4], kl4[4];
                const uint32_t off = (uint32_t)j * 16 * KP + ks * 32;
                ldsm_x4(kh4, kBaseH + off);
                ldsm_x4(kl4, kBaseL + off);
                mma_bf16(s[2 * j],     qh[ks], &kh4[0]);
                mma_bf16(s[2 * j],     qh[ks], &kl4[0]);
                mma_bf16(s[2 * j],     ql[ks], &kh4[0]);
                mma_bf16(s[2 * j + 1], qh[ks], &kh4[2]);
                mma_bf16(s[2 * j + 1], qh[ks], &kl4[2]);
                mma_bf16(s[2 * j + 1], ql[ks], &kh4[2]);
            }
        }

        if (jt == jmax) {
            #pragma unroll
            for (int an = 0; an < 8; an++) {
                int c0 = an * 8 + 2 * q, c1 = c0 + 1;
                if (c0 > rloc)     s[an][0] = -1e9f;
                if (c1 > rloc)     s[an][1] = -1e9f;
                if (c0 > rloc + 8) s[an][2] = -1e9f;
                if (c1 > rloc + 8) s[an][3] = -1e9f;
            }
        }

        float mx0 = -1e30f, mx1 = -1e30f;
        #pragma unroll
        for (int an = 0; an < 8; an++) {
            mx0 = fmaxf(mx0, fmaxf(s[an][0], s[an][1]));
            mx1 = fmaxf(mx1, fmaxf(s[an][2], s[an][3]));
        }
        mx0 = fmaxf(mx0, __shfl_xor_sync(0xFFFFFFFF, mx0, 1));
        mx0 = fmaxf(mx0, __shfl_xor_sync(0xFFFFFFFF, mx0, 2));
        mx1 = fmaxf(mx1, __shfl_xor_sync(0xFFFFFFFF, mx1, 1));
        mx1 = fmaxf(mx1, __shfl_xor_sync(0xFFFFFFFF, mx1, 2));
        float mn0 = fmaxf(m0, mx0), mn1 = fmaxf(m1, mx1);
        float a0 = __expf(m0 - mn0), a1 = __expf(m1 - mn1);
        float sum0 = 0.f, sum1 = 0.f;
        #pragma unroll
        for (int an = 0; an < 8; an++) {
            s[an][0] = __expf(s[an][0] - mn0);
            s[an][1] = __expf(s[an][1] - mn0);
            s[an][2] = __expf(s[an][2] - mn1);
            s[an][3] = __expf(s[an][3] - mn1);
            sum0 += s[an][0] + s[an][1];
            sum1 += s[an][2] + s[an][3];
        }
        sum0 += __shfl_xor_sync(0xFFFFFFFF, sum0, 1);
        sum0 += __shfl_xor_sync(0xFFFFFFFF, sum0, 2);
        sum1 += __shfl_xor_sync(0xFFFFFFFF, sum1, 1);
        sum1 += __shfl_xor_sync(0xFFFFFFFF, sum1, 2);
        l0 = l0 * a0 + sum0;  l1 = l1 * a1 + sum1;
        m0 = mn0;  m1 = mn1;
        #pragma unroll
        for (int an = 0; an < 8; an++) {
            o[an][0] *= a0; o[an][1] *= a0;
            o[an][2] *= a1; o[an][3] *= a1;
        }

        uint32_t ph[4][4], pl[4][4];
        #pragma unroll
        for (int kb = 0; kb < 4; kb++) {
            split2(s[2 * kb][0],     s[2 * kb][1],     ph[kb][0], pl[kb][0]);
            split2(s[2 * kb][2],     s[2 * kb][3],     ph[kb][1], pl[kb][1]);
            split2(s[2 * kb + 1][0], s[2 * kb + 1][1], ph[kb][2], pl[kb][2]);
            split2(s[2 * kb + 1][2], s[2 * kb + 1][3], ph[kb][3], pl[kb][3]);
        }

        // O += Ph*Vh + Ph*Vl + Pl*Vh  (V via ldmatrix.trans from [t][64])
        #pragma unroll
        for (int kb = 0; kb < 4; kb++) {
            #pragma unroll
            for (int j = 0; j < 4; j++) {
                uint32_t vh4[4], vl4[4];
                const uint32_t off = (uint32_t)kb * 16 * KP + j * 32;
                ldsm_x4_trans(vh4, vBaseH + off);
                ldsm_x4_trans(vl4, vBaseL + off);
                mma_bf16(o[2 * j],     ph[kb], &vh4[0]);
                mma_bf16(o[2 * j],     ph[kb], &vl4[0]);
                mma_bf16(o[2 * j],     pl[kb], &vh4[0]);
                mma_bf16(o[2 * j + 1], ph[kb], &vh4[2]);
                mma_bf16(o[2 * j + 1], ph[kb], &vl4[2]);
                mma_bf16(o[2 * j + 1], pl[kb], &vh4[2]);
            }
        }
    }

    const float li0 = 1.f / l0, li1 = 1.f / l1;
    const size_t row0 = (size_t)b * SEQ + i0 + rloc;
    #pragma unroll
    for (int an = 0; an < 8; an++) {
        const int col = h * DK + an * 8 + 2 * q;
        uint32_t hi, lo;
        split2(o[an][0] * li0, o[an][1] * li0, hi, lo);
        *(uint32_t*)(g_A_hi + row0 * D_MODEL + col) = hi;
        *(uint32_t*)(g_A_lo + row0 * D_MODEL + col) = lo;
        split2(o[an][2] * li1, o[an][3] * li1, hi, lo);
        *(uint32_t*)(g_A_hi + (row0 + 8) * D_MODEL + col) = hi;
        *(uint32_t*)(g_A_lo + (row0 + 8) * D_MODEL + col) = lo;
    }
}

// ---------------------------------------------------------------------------
extern "C" void kernel_launch(void* const* d_in, const int* in_sizes, int n_in,
                              void* d_out, int out_size)
{
    const float* x     = (const float*)d_in[0];
    const float* Wqkv  = (const float*)d_in[1];
    const float* Wproj = (const float*)d_in[2];
    float* out = (float*)d_out;

    const int GEMM_SMEM  = 2 * BUFSZ;   // 80 KB
    const int FLASH_SMEM = 2 * FBUF;    // 72 KB
    cudaFuncSetAttribute(mma_gemm<true>,
                         cudaFuncAttributeMaxDynamicSharedMemorySize, GEMM_SMEM);
    cudaFuncSetAttribute(mma_gemm<false>,
                         cudaFuncAttributeMaxDynamicSharedMemorySize, GEMM_SMEM);
    cudaFuncSetAttribute(flash_mma,
                         cudaFuncAttributeMaxDynamicSharedMemorySize, FLASH_SMEM);

    // weight prepasses
    wprep_kernel<0><<<dim3(3 * D_MODEL / 32, D_MODEL / 32), dim3(32, 8)>>>(Wqkv, 3 * D_MODEL);
    wprep_kernel<1><<<dim3(D_MODEL / 32, D_MODEL / 32), dim3(32, 8)>>>(Wproj, D_MODEL);

    // x -> hi/lo
    aprep_kernel<<<(size_t)MTOT * D_MODEL / 4 / 256, 256>>>(x);

    // qkv GEMM with fused split epilogue -> g_Qh/Ql, g_Kh/Kl, g_Vh/Vl
    mma_gemm<true><<<dim3(3 * D_MODEL / 128, MTOT / 128), 256, GEMM_SMEM>>>(nullptr);

    // tensor-core flash attention (reversed scheduling, 3 CTAs/SM)
    flash_mma<<<dim3(SEQ / 64, BH), 128, FLASH_SMEM>>>();

    // out = attn @ W_proj
    mma_gemm<false><<<dim3(D_MODEL / 128, MTOT / 128), 256, GEMM_SMEM>>>(out);
}